// round 12
// baseline (speedup 1.0000x reference)
#include <cuda_runtime.h>
#include <cuda_fp16.h>

#define NN      50000      // nodes
#define NIN     128        // node in-dim
#define NOUT    64         // node out-dim
#define EIN     32         // edge feat dim
#define NE      400000     // undirected edges
#define ND      (2*NE)     // directed edges
#define ALPHA_L 0.2f
#define EPSV    1e-12f
#define NPART   256
#define FULLM   0xffffffffu

// ---------------- scratch (device globals) -------------------------------------
__device__ __align__(16) __half g_hvh[NN * NOUT];  // h_v in fp16 (gather path)
__device__ __align__(16) __half g_msgh[NN * NOUT]; // segment sum by src (fp16)
__device__ __align__(8) float2 g_s12[NN];          // packed (s1, s2) per node
__device__ float  g_hn[NN];
__device__ float  g_attsum[NN];
__device__ float  g_lr[ND];
__device__ double g_psum[NPART];
__device__ double g_psq[NPART];

// fp16x2 vector RED, 16B: 8 halves in one L2 atomic op (sm_90+)
__device__ __forceinline__ void red_h8(__half* addr, unsigned int r0, unsigned int r1,
                                       unsigned int r2, unsigned int r3) {
    asm volatile("red.global.add.noftz.v4.f16x2 [%0], {%1, %2, %3, %4};"
                 :: "l"(addr), "r"(r0), "r"(r1), "r"(r2), "r"(r3) : "memory");
}
__device__ __forceinline__ __half2 u32_as_h2(unsigned int u) {
    __half2 h; *reinterpret_cast<unsigned int*>(&h) = u; return h;
}
__device__ __forceinline__ unsigned int h2_as_u32(__half2 h) {
    return *reinterpret_cast<unsigned int*>(&h);
}
// packed fp32x2 FMA (PTX-only path to FFMA2)
__device__ __forceinline__ void fma2(unsigned long long& d,
                                     unsigned long long a,
                                     unsigned long long b) {
    asm("fma.rn.f32x2 %0, %1, %2, %0;" : "+l"(d) : "l"(a), "l"(b));
}
__device__ __forceinline__ unsigned long long pack2(float v) {
    unsigned long long r; unsigned int u = __float_as_uint(v);
    asm("mov.b64 %0, {%1, %1};" : "=l"(r) : "r"(u));
    return r;
}
__device__ __forceinline__ float2 unpack2(unsigned long long p) {
    unsigned int lo, hi;
    asm("mov.b64 {%0, %1}, %2;" : "=r"(lo), "=r"(hi) : "l"(p));
    return make_float2(__uint_as_float(lo), __uint_as_float(hi));
}

// ---------------- k1: zero prologue + FFMA2 GEMM + scalars + out[:,0:64] + hvh ---
// 256 threads, 128 nodes/block. Nodes pre-paired in smem (float2 per k), so the
// FFMA2 a-operand is a native LDS.64 broadcast. Thread tile: 4 node-pairs x 4 cols.
__global__ void __launch_bounds__(256) k1_gemm(const float* __restrict__ nf,
                        const float* __restrict__ W,
                        const float* __restrict__ b,
                        const float* __restrict__ an,
                        float* __restrict__ out) {
    extern __shared__ float sm[];
    float* Ws  = sm;           // 8192 floats (32 KB), k-major [128][64]
    float* Ns2 = sm + 8192;    // 16384 floats (64 KB): [64 pairs][128 k][2]
    int tid = threadIdx.x;
    int base = blockIdx.x * 128;
    int gid = blockIdx.x * 256 + tid;

    // prologue: zero attsum + variance partials (grid = 100096 >= NN)
    if (gid < NN) g_attsum[gid] = 0.f;
    if (gid < NPART) { g_psum[gid] = 0.0; g_psq[gid] = 0.0; }

    for (int i = tid; i < (NIN * NOUT) / 4; i += 256)
        ((float4*)Ws)[i] = ((const float4*)W)[i];
    // node tile, pair-interleaved: Ns2[(pair*128 + k)*2 + (node&1)]
    for (int i = tid; i < 128 * 32; i += 256) {
        int r = i >> 5, c = i & 31;          // node-local row, float4 quarter
        int node = base + r;
        float4 v = make_float4(0.f, 0.f, 0.f, 0.f);
        if (node < NN) v = ((const float4*)nf)[(long)node * 32 + c];
        float* dst = Ns2 + ((r >> 1) * 128 + c * 4) * 2 + (r & 1);
        dst[0] = v.x; dst[2] = v.y; dst[4] = v.z; dst[6] = v.w;
    }
    __syncthreads();

    int cg  = tid & 15;        // cols cg*4 .. cg*4+3
    int png = tid >> 4;        // pairs png*4 .. png*4+3 (nodes 8*png .. 8*png+7)

    unsigned long long acc[4][4];
#pragma unroll
    for (int p = 0; p < 4; p++)
#pragma unroll
        for (int j = 0; j < 4; j++) acc[p][j] = 0ULL;

    const float2* nb = (const float2*)Ns2 + (long)png * 4 * 128;

#pragma unroll 8
    for (int k = 0; k < NIN; k++) {
        float4 wv = *(const float4*)&Ws[k * NOUT + cg * 4];
        unsigned long long w0 = pack2(wv.x);
        unsigned long long w1 = pack2(wv.y);
        unsigned long long w2 = pack2(wv.z);
        unsigned long long w3 = pack2(wv.w);
#pragma unroll
        for (int p = 0; p < 4; p++) {
            unsigned long long av =
                *(const unsigned long long*)(nb + p * 128 + k);
            fma2(acc[p][0], av, w0);
            fma2(acc[p][1], av, w1);
            fma2(acc[p][2], av, w2);
            fma2(acc[p][3], av, w3);
        }
    }

    float4 bv = *(const float4*)&b[cg * 4];
    __syncthreads();                         // done reading Ns2; reuse as hvt
    float* hvt = Ns2;                        // 128 x 64 fp32 tile
#pragma unroll
    for (int p = 0; p < 4; p++) {
        float2 u0 = unpack2(acc[p][0]);
        float2 u1 = unpack2(acc[p][1]);
        float2 u2 = unpack2(acc[p][2]);
        float2 u3 = unpack2(acc[p][3]);
        float4 f0 = make_float4(u0.x + bv.x, u1.x + bv.y, u2.x + bv.z, u3.x + bv.w);
        float4 f1 = make_float4(u0.y + bv.x, u1.y + bv.y, u2.y + bv.z, u3.y + bv.w);
        int nl0 = 8 * png + 2 * p;           // even node local idx
        int node0 = base + nl0;
        if (node0 < NN) {
            ((float4*)out)[(long)node0 * 32 + cg] = f0;
            __half2 h01 = __floats2half2_rn(f0.x, f0.y);
            __half2 h23 = __floats2half2_rn(f0.z, f0.w);
            ((uint2*)g_hvh)[(long)node0 * 16 + cg] =
                make_uint2(h2_as_u32(h01), h2_as_u32(h23));
        }
        if (node0 + 1 < NN) {
            ((float4*)out)[(long)(node0 + 1) * 32 + cg] = f1;
            __half2 h01 = __floats2half2_rn(f1.x, f1.y);
            __half2 h23 = __floats2half2_rn(f1.z, f1.w);
            ((uint2*)g_hvh)[(long)(node0 + 1) * 16 + cg] =
                make_uint2(h2_as_u32(h01), h2_as_u32(h23));
        }
        *(float4*)&hvt[nl0 * NOUT + cg * 4]       = f0;
        *(float4*)&hvt[(nl0 + 1) * NOUT + cg * 4] = f1;
    }
    __syncthreads();

    // per-node scalars: 8 warps x 16 nodes each
    int wp = tid >> 5, l = tid & 31;
    float a1x = __ldg(&an[2*l]),      a1y = __ldg(&an[2*l+1]);
    float a2x = __ldg(&an[64 + 2*l]), a2y = __ldg(&an[64 + 2*l+1]);
#pragma unroll
    for (int i = 0; i < 16; i++) {
        int n = wp * 16 + i;
        int node = base + n;
        float2 h = ((const float2*)hvt)[n * 32 + l];
        float s1 = h.x * a1x + h.y * a1y;
        float s2 = h.x * a2x + h.y * a2y;
        float sq = h.x * h.x + h.y * h.y;
#pragma unroll
        for (int o = 16; o; o >>= 1) {
            s1 += __shfl_down_sync(FULLM, s1, o);
            s2 += __shfl_down_sync(FULLM, s2, o);
            sq += __shfl_down_sync(FULLM, sq, o);
        }
        if (l == 0 && node < NN) {
            g_s12[node] = make_float2(s1, s2);
            g_hn[node] = sqrtf(sq);
        }
    }
}

// ---------------- kE: edge dot + attention (both dirs) + zero g_msgh -------------
// Warp = 16 undirected edges (2KB coalesced ef read). All 32 lanes then own one
// (edge, direction) pair. (s1,s2) packed per node -> 2 sectors/edge not 4.
__global__ void kE_edge(const float* __restrict__ ef,
                        const float* __restrict__ an,
                        const int* __restrict__ p) {
    long gid = (long)blockIdx.x * blockDim.x + threadIdx.x;
    // zero msg: 800000 threads cover 800000 uint2 (= 3.2M halves) exactly
    ((uint2*)g_msgh)[gid] = make_uint2(0u, 0u);

    int w = (int)(gid >> 5);
    int l = threadIdx.x & 31;
    int row0 = w * 16;                       // NE % 16 == 0, grid exact
    const float4* ef4 = (const float4*)ef + (long)row0 * 8;
    float4 v0 = __ldg(&ef4[l]);
    float4 v1 = __ldg(&ef4[32 + l]);
    float4 v2 = __ldg(&ef4[64 + l]);
    float4 v3 = __ldg(&ef4[96 + l]);
    const float* a3 = an + 2 * NOUT;
    int q = l & 7;
    float ax = __ldg(&a3[4*q]),   ay = __ldg(&a3[4*q+1]);
    float az = __ldg(&a3[4*q+2]), aw = __ldg(&a3[4*q+3]);
    float s0 = v0.x*ax + v0.y*ay + v0.z*az + v0.w*aw;
    float s1 = v1.x*ax + v1.y*ay + v1.z*az + v1.w*aw;
    float s2 = v2.x*ax + v2.y*ay + v2.z*az + v2.w*aw;
    float s3 = v3.x*ax + v3.y*ay + v3.z*az + v3.w*aw;
#pragma unroll
    for (int o = 4; o; o >>= 1) {
        s0 += __shfl_xor_sync(FULLM, s0, o);
        s1 += __shfl_xor_sync(FULLM, s1, o);
        s2 += __shfl_xor_sync(FULLM, s2, o);
        s3 += __shfl_xor_sync(FULLM, s3, o);
    }
    int e = l & 15, dir = l >> 4;
    int srcl = (e & 3) << 3;
    float t0 = __shfl_sync(FULLM, s0, srcl);
    float t1 = __shfl_sync(FULLM, s1, srcl);
    float t2 = __shfl_sync(FULLM, s2, srcl);
    float t3 = __shfl_sync(FULLM, s3, srcl);
    int c = e >> 2;
    float tu = (c == 0) ? t0 : (c == 1) ? t1 : (c == 2) ? t2 : t3;

    int u = row0 + e;
    int2 xy = __ldg(&((const int2*)p)[u]);
    int src = dir ? xy.y : xy.x;
    int dst = dir ? xy.x : xy.y;
    float2 ssrc = __ldg(&g_s12[src]);
    float2 sdst = __ldg(&g_s12[dst]);
    float lg = ssrc.x + sdst.y + tu;         // s1[src] + s2[dst] + t
    float lr = (lg > 0.f) ? lg : ALPHA_L * lg;
    g_lr[u + dir * NE] = lr;
    atomicAdd(&g_attsum[src], __expf(lr));
}

// ---------------- k4: msg scatter (16B fp16 gather + 16B fp16 RED) ---------------
// 8 lanes per direction; one instruction covers 2 edges (4 directions).
#define ED 8   // undirected edges per warp
__global__ void k4_scatter(const int* __restrict__ p) {
    __shared__ float ssum[8], ssq[8];
    int warp = (blockIdx.x * blockDim.x + threadIdx.x) >> 5;
    int l = threadIdx.x & 31;
    int dgrp = l >> 3, q8 = l & 7;         // direction group 0..3, 16B quarter
    long base = (long)warp * ED;           // NE % ED == 0, grid exact

    int2  xy[ED];
    float l1[ED], l2[ED];
#pragma unroll
    for (int e = 0; e < ED; e++) {
        long u = base + e;
        xy[e] = __ldg(&((const int2*)p)[u]);
        l1[e] = __ldg(&g_lr[u]);
        l2[e] = __ldg(&g_lr[u + NE]);
    }
    float a1[ED], a2[ED];
#pragma unroll
    for (int e = 0; e < ED; e++) {
        a1[e] = __ldg(&g_attsum[xy[e].x]);
        a2[e] = __ldg(&g_attsum[xy[e].y]);
    }
    // gathers: iteration i covers edges 2i (dgrp 0,1) and 2i+1 (dgrp 2,3)
    uint4 h[ED / 2];
#pragma unroll
    for (int i = 0; i < ED / 2; i++) {
        int e0 = 2 * i, e1 = 2 * i + 1;
        int dst = (dgrp == 0) ? xy[e0].y : (dgrp == 1) ? xy[e0].x
                : (dgrp == 2) ? xy[e1].y : xy[e1].x;
        h[i] = __ldg(&((const uint4*)g_hvh)[(long)dst * 8 + q8]);
    }
    float vs = 0.f, vq = 0.f;
#pragma unroll
    for (int i = 0; i < ED / 2; i++) {
        int e0 = 2 * i, e1 = 2 * i + 1;
        float an00 = l1[e0] - __logf(a1[e0]);
        float an01 = l2[e0] - __logf(a2[e0]);
        float an10 = l1[e1] - __logf(a1[e1]);
        float an11 = l2[e1] - __logf(a2[e1]);
        float an = (dgrp == 0) ? an00 : (dgrp == 1) ? an01
                 : (dgrp == 2) ? an10 : an11;
        int src = (dgrp == 0) ? xy[e0].x : (dgrp == 1) ? xy[e0].y
                : (dgrp == 2) ? xy[e1].x : xy[e1].y;
        float2 f0 = __half22float2(u32_as_h2(h[i].x));
        float2 f1 = __half22float2(u32_as_h2(h[i].y));
        float2 f2 = __half22float2(u32_as_h2(h[i].z));
        float2 f3 = __half22float2(u32_as_h2(h[i].w));
        unsigned int r0 = h2_as_u32(__floats2half2_rn(f0.x * an, f0.y * an));
        unsigned int r1 = h2_as_u32(__floats2half2_rn(f1.x * an, f1.y * an));
        unsigned int r2 = h2_as_u32(__floats2half2_rn(f2.x * an, f2.y * an));
        unsigned int r3 = h2_as_u32(__floats2half2_rn(f3.x * an, f3.y * an));
        red_h8(g_msgh + (long)src * NOUT + q8 * 8, r0, r1, r2, r3);
        if (l == 0) {
            vs += an00 + an01 + an10 + an11;
            vq += an00*an00 + an01*an01 + an10*an10 + an11*an11;
        }
    }
    if (l == 0) { ssum[threadIdx.x >> 5] = vs; ssq[threadIdx.x >> 5] = vq; }
    __syncthreads();
    if (threadIdx.x == 0) {
        float bs = 0.f, bq = 0.f;
#pragma unroll
        for (int i = 0; i < 8; i++) { bs += ssum[i]; bq += ssq[i]; }
        atomicAdd(&g_psum[blockIdx.x & (NPART - 1)], (double)bs);
        atomicAdd(&g_psq [blockIdx.x & (NPART - 1)], (double)bq);
    }
}

// ---------------- k6: agg normalize + out[:,64:128]; block 0 also does variance --
__global__ void k6_final(float* __restrict__ out, const float* __restrict__ scale) {
    __shared__ double sd[NPART], qd[NPART];
    int lane = threadIdx.x & 31;
    int node = ((blockIdx.x * blockDim.x + threadIdx.x) >> 4);  // 16 lanes/node
    int q = lane & 15;
    uint2 mh = __ldg(&((const uint2*)g_msgh)[(long)node * 16 + q]);
    float2 m01 = __half22float2(u32_as_h2(mh.x));
    float2 m23 = __half22float2(u32_as_h2(mh.y));
    float sq = m01.x*m01.x + m01.y*m01.y + m23.x*m23.x + m23.y*m23.y;
#pragma unroll
    for (int o = 8; o; o >>= 1) sq += __shfl_xor_sync(FULLM, sq, o);
    float r = __ldg(&g_hn[node]) * __ldg(scale) / fmaxf(sqrtf(sq), EPSV);
    ((float4*)(out + (long)node * 128))[16 + q] =
        make_float4(m01.x * r, m01.y * r, m23.x * r, m23.y * r);

    if (blockIdx.x == 0) {
        int t = threadIdx.x;
        sd[t] = g_psum[t]; qd[t] = g_psq[t];
        __syncthreads();
        for (int o = NPART / 2; o; o >>= 1) {
            if (t < o) { sd[t] += sd[t + o]; qd[t] += qd[t + o]; }
            __syncthreads();
        }
        if (t == 0) {
            double E = (double)ND;
            double var = (qd[0] - sd[0] * sd[0] / E) / (E - 1.0);
            out[(long)NN * 128] = (float)var;
        }
    }
}

// ---------------- launch --------------------------------------------------------------
extern "C" void kernel_launch(void* const* d_in, const int* in_sizes, int n_in,
                              void* d_out, int out_size) {
    const float* nf    = (const float*)d_in[0];
    const float* ef    = (const float*)d_in[1];
    const int*   edges = (const int*)  d_in[2];
    const float* W     = (const float*)d_in[3];
    const float* b     = (const float*)d_in[4];
    const float* an    = (const float*)d_in[5];
    const float* scale = (const float*)d_in[6];
    float* out = (float*)d_out;

    const int k1_smem = (8192 + 16384) * 4;  // 96 KB
    cudaFuncSetAttribute(k1_gemm, cudaFuncAttributeMaxDynamicSharedMemorySize, k1_smem);

    k1_gemm   <<<(NN + 127)/128, 256, k1_smem>>>(nf, W, b, an, out);
    kE_edge   <<<NE/16/8, 256>>>(ef, an, edges);     // 3125 blocks, warp = 16 edges
    k4_scatter<<<NE/(8*ED), 256>>>(edges);           // 6250 blocks, warp = 8 edges
    k6_final  <<<NN/16, 256>>>(out, scale);          // 3125 blocks, 16 nodes/block
}

// round 13
// speedup vs baseline: 1.0899x; 1.0899x over previous
#include <cuda_runtime.h>
#include <cuda_fp16.h>

#define NN      50000      // nodes
#define NIN     128        // node in-dim
#define NOUT    64         // node out-dim
#define EIN     32         // edge feat dim
#define NE      400000     // undirected edges
#define ND      (2*NE)     // directed edges
#define ALPHA_L 0.2f
#define EPSV    1e-12f
#define NPART   256
#define FULLM   0xffffffffu

// ---------------- scratch (device globals) -------------------------------------
__device__ __align__(16) __half g_hvh[NN * NOUT];  // h_v in fp16 (gather path)
__device__ __align__(16) __half g_msgh[NN * NOUT]; // segment sum by src (fp16)
__device__ __align__(8) float2 g_s12[NN];          // packed (s1, s2) per node
__device__ float  g_hn[NN];
__device__ float  g_attsum[NN];
__device__ float  g_lr[ND];
__device__ double g_psum[NPART];
__device__ double g_psq[NPART];

// fp16x2 vector RED: 4 halves in one L2 atomic op (sm_90+)
__device__ __forceinline__ void red_h4(__half* addr, __half2 a, __half2 b) {
    asm volatile("red.global.add.noftz.v2.f16x2 [%0], {%1, %2};"
                 :: "l"(addr),
                    "r"(*reinterpret_cast<unsigned int*>(&a)),
                    "r"(*reinterpret_cast<unsigned int*>(&b)) : "memory");
}
__device__ __forceinline__ __half2 u32_as_h2(unsigned int u) {
    __half2 h; *reinterpret_cast<unsigned int*>(&h) = u; return h;
}
__device__ __forceinline__ unsigned int h2_as_u32(__half2 h) {
    return *reinterpret_cast<unsigned int*>(&h);
}
// packed fp32x2 FMA (PTX-only path to FFMA2)
__device__ __forceinline__ void fma2(unsigned long long& d,
                                     unsigned long long a,
                                     unsigned long long b) {
    asm("fma.rn.f32x2 %0, %1, %2, %0;" : "+l"(d) : "l"(a), "l"(b));
}
__device__ __forceinline__ unsigned long long pack2(float v) {
    unsigned long long r; unsigned int u = __float_as_uint(v);
    asm("mov.b64 %0, {%1, %1};" : "=l"(r) : "r"(u));
    return r;
}
__device__ __forceinline__ float2 unpack2(unsigned long long p) {
    unsigned int lo, hi;
    asm("mov.b64 {%0, %1}, %2;" : "=r"(lo), "=r"(hi) : "l"(p));
    return make_float2(__uint_as_float(lo), __uint_as_float(hi));
}

// ---------------- k1: zero prologue + FFMA2 GEMM + scalars + out[:,0:64] + hvh ---
// 256 threads, 128 nodes/block. Nodes pre-paired in smem (float2 per k), so the
// FFMA2 a-operand is a native LDS.64 broadcast. Thread tile: 4 node-pairs x 4 cols.
__global__ void __launch_bounds__(256) k1_gemm(const float* __restrict__ nf,
                        const float* __restrict__ W,
                        const float* __restrict__ b,
                        const float* __restrict__ an,
                        float* __restrict__ out) {
    extern __shared__ float sm[];
    float* Ws  = sm;           // 8192 floats (32 KB), k-major [128][64]
    float* Ns2 = sm + 8192;    // 16384 floats (64 KB): [64 pairs][128 k][2]
    int tid = threadIdx.x;
    int base = blockIdx.x * 128;
    int gid = blockIdx.x * 256 + tid;

    // prologue: zero attsum + variance partials (grid = 100096 >= NN)
    if (gid < NN) g_attsum[gid] = 0.f;
    if (gid < NPART) { g_psum[gid] = 0.0; g_psq[gid] = 0.0; }

    for (int i = tid; i < (NIN * NOUT) / 4; i += 256)
        ((float4*)Ws)[i] = ((const float4*)W)[i];
    // node tile, pair-interleaved: Ns2[(pair*128 + k)*2 + (node&1)]
    for (int i = tid; i < 128 * 32; i += 256) {
        int r = i >> 5, c = i & 31;          // node-local row, float4 quarter
        int node = base + r;
        float4 v = make_float4(0.f, 0.f, 0.f, 0.f);
        if (node < NN) v = ((const float4*)nf)[(long)node * 32 + c];
        float* dst = Ns2 + ((r >> 1) * 128 + c * 4) * 2 + (r & 1);
        dst[0] = v.x; dst[2] = v.y; dst[4] = v.z; dst[6] = v.w;
    }
    __syncthreads();

    int cg  = tid & 15;        // cols cg*4 .. cg*4+3
    int png = tid >> 4;        // pairs png*4 .. png*4+3 (nodes 8*png .. 8*png+7)

    unsigned long long acc[4][4];
#pragma unroll
    for (int p = 0; p < 4; p++)
#pragma unroll
        for (int j = 0; j < 4; j++) acc[p][j] = 0ULL;

    const float2* nb = (const float2*)Ns2 + (long)png * 4 * 128;

#pragma unroll 8
    for (int k = 0; k < NIN; k++) {
        float4 wv = *(const float4*)&Ws[k * NOUT + cg * 4];
        unsigned long long w0 = pack2(wv.x);
        unsigned long long w1 = pack2(wv.y);
        unsigned long long w2 = pack2(wv.z);
        unsigned long long w3 = pack2(wv.w);
#pragma unroll
        for (int p = 0; p < 4; p++) {
            unsigned long long av =
                *(const unsigned long long*)(nb + p * 128 + k);
            fma2(acc[p][0], av, w0);
            fma2(acc[p][1], av, w1);
            fma2(acc[p][2], av, w2);
            fma2(acc[p][3], av, w3);
        }
    }

    float4 bv = *(const float4*)&b[cg * 4];
    __syncthreads();                         // done reading Ns2; reuse as hvt
    float* hvt = Ns2;                        // 128 x 64 fp32 tile
#pragma unroll
    for (int p = 0; p < 4; p++) {
        float2 u0 = unpack2(acc[p][0]);
        float2 u1 = unpack2(acc[p][1]);
        float2 u2 = unpack2(acc[p][2]);
        float2 u3 = unpack2(acc[p][3]);
        float4 f0 = make_float4(u0.x + bv.x, u1.x + bv.y, u2.x + bv.z, u3.x + bv.w);
        float4 f1 = make_float4(u0.y + bv.x, u1.y + bv.y, u2.y + bv.z, u3.y + bv.w);
        int nl0 = 8 * png + 2 * p;           // even node local idx
        int node0 = base + nl0;
        if (node0 < NN) {
            ((float4*)out)[(long)node0 * 32 + cg] = f0;
            __half2 h01 = __floats2half2_rn(f0.x, f0.y);
            __half2 h23 = __floats2half2_rn(f0.z, f0.w);
            ((uint2*)g_hvh)[(long)node0 * 16 + cg] =
                make_uint2(h2_as_u32(h01), h2_as_u32(h23));
        }
        if (node0 + 1 < NN) {
            ((float4*)out)[(long)(node0 + 1) * 32 + cg] = f1;
            __half2 h01 = __floats2half2_rn(f1.x, f1.y);
            __half2 h23 = __floats2half2_rn(f1.z, f1.w);
            ((uint2*)g_hvh)[(long)(node0 + 1) * 16 + cg] =
                make_uint2(h2_as_u32(h01), h2_as_u32(h23));
        }
        *(float4*)&hvt[nl0 * NOUT + cg * 4]       = f0;
        *(float4*)&hvt[(nl0 + 1) * NOUT + cg * 4] = f1;
    }
    __syncthreads();

    // per-node scalars: 8 warps x 16 nodes each
    int wp = tid >> 5, l = tid & 31;
    float a1x = __ldg(&an[2*l]),      a1y = __ldg(&an[2*l+1]);
    float a2x = __ldg(&an[64 + 2*l]), a2y = __ldg(&an[64 + 2*l+1]);
#pragma unroll
    for (int i = 0; i < 16; i++) {
        int n = wp * 16 + i;
        int node = base + n;
        float2 h = ((const float2*)hvt)[n * 32 + l];
        float s1 = h.x * a1x + h.y * a1y;
        float s2 = h.x * a2x + h.y * a2y;
        float sq = h.x * h.x + h.y * h.y;
#pragma unroll
        for (int o = 16; o; o >>= 1) {
            s1 += __shfl_down_sync(FULLM, s1, o);
            s2 += __shfl_down_sync(FULLM, s2, o);
            sq += __shfl_down_sync(FULLM, sq, o);
        }
        if (l == 0 && node < NN) {
            g_s12[node] = make_float2(s1, s2);
            g_hn[node] = sqrtf(sq);
        }
    }
}

// ---------------- kE: edge dot + attention (both dirs) + zero g_msgh -------------
// Warp = 16 undirected edges (2KB coalesced ef read). All 32 lanes then own one
// (edge, direction) pair. (s1,s2) packed per node -> 2 sectors/edge not 4.
__global__ void kE_edge(const float* __restrict__ ef,
                        const float* __restrict__ an,
                        const int* __restrict__ p) {
    long gid = (long)blockIdx.x * blockDim.x + threadIdx.x;
    // zero msg: 800000 threads cover 800000 uint2 (= 3.2M halves) exactly
    ((uint2*)g_msgh)[gid] = make_uint2(0u, 0u);

    int w = (int)(gid >> 5);
    int l = threadIdx.x & 31;
    int row0 = w * 16;                       // NE % 16 == 0, grid exact
    const float4* ef4 = (const float4*)ef + (long)row0 * 8;
    float4 v0 = __ldg(&ef4[l]);
    float4 v1 = __ldg(&ef4[32 + l]);
    float4 v2 = __ldg(&ef4[64 + l]);
    float4 v3 = __ldg(&ef4[96 + l]);
    const float* a3 = an + 2 * NOUT;
    int q = l & 7;
    float ax = __ldg(&a3[4*q]),   ay = __ldg(&a3[4*q+1]);
    float az = __ldg(&a3[4*q+2]), aw = __ldg(&a3[4*q+3]);
    float s0 = v0.x*ax + v0.y*ay + v0.z*az + v0.w*aw;
    float s1 = v1.x*ax + v1.y*ay + v1.z*az + v1.w*aw;
    float s2 = v2.x*ax + v2.y*ay + v2.z*az + v2.w*aw;
    float s3 = v3.x*ax + v3.y*ay + v3.z*az + v3.w*aw;
#pragma unroll
    for (int o = 4; o; o >>= 1) {
        s0 += __shfl_xor_sync(FULLM, s0, o);
        s1 += __shfl_xor_sync(FULLM, s1, o);
        s2 += __shfl_xor_sync(FULLM, s2, o);
        s3 += __shfl_xor_sync(FULLM, s3, o);
    }
    int e = l & 15, dir = l >> 4;
    int srcl = (e & 3) << 3;
    float t0 = __shfl_sync(FULLM, s0, srcl);
    float t1 = __shfl_sync(FULLM, s1, srcl);
    float t2 = __shfl_sync(FULLM, s2, srcl);
    float t3 = __shfl_sync(FULLM, s3, srcl);
    int c = e >> 2;
    float tu = (c == 0) ? t0 : (c == 1) ? t1 : (c == 2) ? t2 : t3;

    int u = row0 + e;
    int2 xy = __ldg(&((const int2*)p)[u]);
    int src = dir ? xy.y : xy.x;
    int dst = dir ? xy.x : xy.y;
    float2 ssrc = __ldg(&g_s12[src]);
    float2 sdst = __ldg(&g_s12[dst]);
    float lg = ssrc.x + sdst.y + tu;         // s1[src] + s2[dst] + t
    float lr = (lg > 0.f) ? lg : ALPHA_L * lg;
    g_lr[u + dir * NE] = lr;
    atomicAdd(&g_attsum[src], __expf(lr));
}

// ---------------- k4: msg scatter (fp16 gather + fp16 RED) + var partials --------
// Round-11 validated form: 16 lanes per direction, 8B v2.f16x2 REDs.
#define ED 8   // undirected edges per warp
__global__ void k4_scatter(const int* __restrict__ p) {
    __shared__ float ssum[8], ssq[8];
    int warp = (blockIdx.x * blockDim.x + threadIdx.x) >> 5;
    int l = threadIdx.x & 31;
    int half = l >> 4, q = l & 15;
    long base = (long)warp * ED;           // NE % ED == 0, grid exact

    int2  xy[ED];
    float l1[ED], l2[ED];
#pragma unroll
    for (int e = 0; e < ED; e++) {
        long u = base + e;
        xy[e] = __ldg(&((const int2*)p)[u]);
        l1[e] = __ldg(&g_lr[u]);
        l2[e] = __ldg(&g_lr[u + NE]);
    }
    float a1[ED], a2[ED];
    uint2 h[ED];
#pragma unroll
    for (int e = 0; e < ED; e++) {
        a1[e] = __ldg(&g_attsum[xy[e].x]);
        a2[e] = __ldg(&g_attsum[xy[e].y]);
        int gdst = half ? xy[e].x : xy[e].y;
        h[e] = __ldg(&((const uint2*)g_hvh)[(long)gdst * 16 + q]);  // 4 halves
    }
    float vs = 0.f, vq = 0.f;
#pragma unroll
    for (int e = 0; e < ED; e++) {
        float an1 = l1[e] - __logf(a1[e]);
        float an2 = l2[e] - __logf(a2[e]);
        float an  = half ? an2 : an1;
        int gsrc  = half ? xy[e].y : xy[e].x;
        float2 f01 = __half22float2(u32_as_h2(h[e].x));
        float2 f23 = __half22float2(u32_as_h2(h[e].y));
        __half2 p01 = __floats2half2_rn(f01.x * an, f01.y * an);
        __half2 p23 = __floats2half2_rn(f23.x * an, f23.y * an);
        red_h4(g_msgh + (long)gsrc * NOUT + q * 4, p01, p23);
        if (l == 0) { vs += an1 + an2; vq += an1 * an1 + an2 * an2; }
    }
    if (l == 0) { ssum[threadIdx.x >> 5] = vs; ssq[threadIdx.x >> 5] = vq; }
    __syncthreads();
    if (threadIdx.x == 0) {
        float bs = 0.f, bq = 0.f;
#pragma unroll
        for (int i = 0; i < 8; i++) { bs += ssum[i]; bq += ssq[i]; }
        atomicAdd(&g_psum[blockIdx.x & (NPART - 1)], (double)bs);
        atomicAdd(&g_psq [blockIdx.x & (NPART - 1)], (double)bq);
    }
}

// ---------------- k6: agg normalize + out[:,64:128]; block 0 also does variance --
__global__ void k6_final(float* __restrict__ out, const float* __restrict__ scale) {
    __shared__ double sd[NPART], qd[NPART];
    int lane = threadIdx.x & 31;
    int node = ((blockIdx.x * blockDim.x + threadIdx.x) >> 4);  // 16 lanes/node
    int q = lane & 15;
    uint2 mh = __ldg(&((const uint2*)g_msgh)[(long)node * 16 + q]);
    float2 m01 = __half22float2(u32_as_h2(mh.x));
    float2 m23 = __half22float2(u32_as_h2(mh.y));
    float sq = m01.x*m01.x + m01.y*m01.y + m23.x*m23.x + m23.y*m23.y;
#pragma unroll
    for (int o = 8; o; o >>= 1) sq += __shfl_xor_sync(FULLM, sq, o);
    float r = __ldg(&g_hn[node]) * __ldg(scale) / fmaxf(sqrtf(sq), EPSV);
    ((float4*)(out + (long)node * 128))[16 + q] =
        make_float4(m01.x * r, m01.y * r, m23.x * r, m23.y * r);

    if (blockIdx.x == 0) {
        int t = threadIdx.x;
        sd[t] = g_psum[t]; qd[t] = g_psq[t];
        __syncthreads();
        for (int o = NPART / 2; o; o >>= 1) {
            if (t < o) { sd[t] += sd[t + o]; qd[t] += qd[t + o]; }
            __syncthreads();
        }
        if (t == 0) {
            double E = (double)ND;
            double var = (qd[0] - sd[0] * sd[0] / E) / (E - 1.0);
            out[(long)NN * 128] = (float)var;
        }
    }
}

// ---------------- launch --------------------------------------------------------------
extern "C" void kernel_launch(void* const* d_in, const int* in_sizes, int n_in,
                              void* d_out, int out_size) {
    const float* nf    = (const float*)d_in[0];
    const float* ef    = (const float*)d_in[1];
    const int*   edges = (const int*)  d_in[2];
    const float* W     = (const float*)d_in[3];
    const float* b     = (const float*)d_in[4];
    const float* an    = (const float*)d_in[5];
    const float* scale = (const float*)d_in[6];
    float* out = (float*)d_out;

    const int k1_smem = (8192 + 16384) * 4;  // 96 KB
    cudaFuncSetAttribute(k1_gemm, cudaFuncAttributeMaxDynamicSharedMemorySize, k1_smem);

    k1_gemm   <<<(NN + 127)/128, 256, k1_smem>>>(nf, W, b, an, out);
    kE_edge   <<<NE/16/8, 256>>>(ef, an, edges);     // 3125 blocks, warp = 16 edges
    k4_scatter<<<NE/(8*ED), 256>>>(edges);           // 6250 blocks, warp = 8 edges
    k6_final  <<<NN/16, 256>>>(out, scale);          // 3125 blocks, 16 nodes/block
}